// round 3
// baseline (speedup 1.0000x reference)
#include <cuda_runtime.h>
#include <math.h>

#define D_MODEL 2048
#define N_EXP   64
#define TOP_K   8
#define BM      64
#define BK      16
#define PANEL   512     // Eigen-style kc panel: serial FMA chain from zero per panel
#define PAD     4
#define MAX_T   16384

// Scratch for logits [T, 64] (device global: no allocations allowed)
__device__ float g_logits[(size_t)MAX_T * N_EXP];

// ---------------------------------------------------------------------------
// GEMM: logits[t][e] = scale * dot(x[t,:], W[e,:])
// Block tile: 64 tokens x 64 experts, K-tile 16. 256 threads, 4x4 reg tile.
//
// Accumulation mimics Eigen gebp blocked summation (the XLA-CPU reference
// path): K split into PANEL=512 chunks; within a chunk, one serial FFMA per
// k in strictly ascending order starting from zero; chunk results added in
// ascending order. All arithmetic through __fmaf_rn/__fadd_rn so the
// compiler cannot re-associate or re-contract the rounding sequence.
// ---------------------------------------------------------------------------
__global__ void __launch_bounds__(256, 2) gemm_logits_kernel(
    const float* __restrict__ x, const float* __restrict__ W,
    float* __restrict__ logits, int T)
{
    __shared__ float xs[BK][BM + PAD];     // xs[k][token]
    __shared__ float ws[BK][N_EXP + PAD];  // ws[k][expert]

    const float scale = 0.022097086912079608f;  // 1/sqrt(2048)

    const int tid     = threadIdx.x;
    const int tokBase = blockIdx.x * BM;

    // compute mapping: 16x16 thread grid, each thread 4 tokens x 4 experts
    const int row = tid >> 4;   // 0..15 -> tokens row*4..row*4+3
    const int col = tid & 15;   // 0..15 -> experts col*4..col*4+3

    // load mapping: each thread loads one float4 of x and one of W per k-tile
    const int ldRow = tid >> 2;        // 0..63 (token or expert row)
    const int ldK   = (tid & 3) << 2;  // 0,4,8,12

    float accT[4][4];  // total (across panels)
#pragma unroll
    for (int i = 0; i < 4; i++)
#pragma unroll
        for (int j = 0; j < 4; j++) accT[i][j] = 0.0f;

    const float* xptr = x + (size_t)(tokBase + ldRow) * D_MODEL + ldK;
    const float* wptr = W + (size_t)ldRow * D_MODEL + ldK;

    for (int pb = 0; pb < D_MODEL; pb += PANEL) {
        float accP[4][4];  // panel accumulator, starts from zero
#pragma unroll
        for (int i = 0; i < 4; i++)
#pragma unroll
            for (int j = 0; j < 4; j++) accP[i][j] = 0.0f;

        for (int kb = pb; kb < pb + PANEL; kb += BK) {
            float4 xv = *reinterpret_cast<const float4*>(xptr + kb);
            float4 wv = *reinterpret_cast<const float4*>(wptr + kb);
            xs[ldK + 0][ldRow] = xv.x;
            xs[ldK + 1][ldRow] = xv.y;
            xs[ldK + 2][ldRow] = xv.z;
            xs[ldK + 3][ldRow] = xv.w;
            ws[ldK + 0][ldRow] = wv.x;
            ws[ldK + 1][ldRow] = wv.y;
            ws[ldK + 2][ldRow] = wv.z;
            ws[ldK + 3][ldRow] = wv.w;
            __syncthreads();

#pragma unroll
            for (int k = 0; k < BK; k++) {
                float4 a = *reinterpret_cast<const float4*>(&xs[k][row << 2]);
                float4 b = *reinterpret_cast<const float4*>(&ws[k][col << 2]);
                const float av[4] = {a.x, a.y, a.z, a.w};
                const float bv[4] = {b.x, b.y, b.z, b.w};
#pragma unroll
                for (int i = 0; i < 4; i++)
#pragma unroll
                    for (int j = 0; j < 4; j++)
                        accP[i][j] = __fmaf_rn(av[i], bv[j], accP[i][j]);
            }
            __syncthreads();
        }

#pragma unroll
        for (int i = 0; i < 4; i++)
#pragma unroll
            for (int j = 0; j < 4; j++)
                accT[i][j] = __fadd_rn(accT[i][j], accP[i][j]);
    }

#pragma unroll
    for (int i = 0; i < 4; i++) {
        int tok = tokBase + (row << 2) + i;
        float4 o;
        o.x = __fmul_rn(accT[i][0], scale);
        o.y = __fmul_rn(accT[i][1], scale);
        o.z = __fmul_rn(accT[i][2], scale);
        o.w = __fmul_rn(accT[i][3], scale);
        *reinterpret_cast<float4*>(&logits[(size_t)tok * N_EXP + (col << 2)]) = o;
    }
}

// ---------------------------------------------------------------------------
// Top-k + masked softmax. One warp per token. 64 logits -> 2 per lane.
// Iterative warp argmax over biased logits (tie -> smaller index, matching
// jax.lax.top_k), then softmax over the 8 selected ORIGINAL logits.
// ---------------------------------------------------------------------------
__global__ void __launch_bounds__(256) topk_softmax_kernel(
    const float* __restrict__ logits, const float* __restrict__ bias,
    float* __restrict__ out, int T, int write_indices)
{
    const int gwarp = (blockIdx.x * blockDim.x + threadIdx.x) >> 5;
    const int lane  = threadIdx.x & 31;
    if (gwarp >= T) return;

    const float NEG_INF = __int_as_float(0xff800000);

    const float* lrow = logits + (size_t)gwarp * N_EXP;
    float v0 = lrow[lane];
    float v1 = lrow[lane + 32];
    float b0 = __fadd_rn(v0, bias[lane]);
    float b1 = __fadd_rn(v1, bias[lane + 32]);

    float selLogit[TOP_K];
    int   selIdx[TOP_K];

#pragma unroll
    for (int k = 0; k < TOP_K; k++) {
        // local best of the two candidates (tie -> smaller index, i.e. b0)
        float bv = b0;
        int   bi = lane;
        if (b1 > b0) { bv = b1; bi = lane + 32; }
        // warp butterfly argmax, tie -> smaller index (consistent on all lanes)
#pragma unroll
        for (int off = 16; off > 0; off >>= 1) {
            float ov = __shfl_xor_sync(0xffffffffu, bv, off);
            int   oi = __shfl_xor_sync(0xffffffffu, bi, off);
            if (ov > bv || (ov == bv && oi < bi)) { bv = ov; bi = oi; }
        }
        // fetch original (scaled) logit at bi
        float cand = (bi < 32) ? v0 : v1;
        selLogit[k] = __shfl_sync(0xffffffffu, cand, bi & 31);
        selIdx[k]   = bi;
        // knock out the winner
        if (lane == (bi & 31)) {
            if (bi < 32) b0 = NEG_INF; else b1 = NEG_INF;
        }
    }

    // softmax over the 8 selected original logits
    float m = selLogit[0];
#pragma unroll
    for (int k = 1; k < TOP_K; k++) m = fmaxf(m, selLogit[k]);
    float e[TOP_K];
    float s = 0.0f;
#pragma unroll
    for (int k = 0; k < TOP_K; k++) { e[k] = __expf(selLogit[k] - m); s += e[k]; }
    float inv = 1.0f / s;

    if (lane == 0) {
        float* wout = out + (size_t)gwarp * TOP_K;
#pragma unroll
        for (int k = 0; k < TOP_K; k++) wout[k] = e[k] * inv;
        if (write_indices) {
            float* iout = out + (size_t)T * TOP_K + (size_t)gwarp * TOP_K;
#pragma unroll
            for (int k = 0; k < TOP_K; k++) iout[k] = (float)selIdx[k];
        }
    }
}

// ---------------------------------------------------------------------------
extern "C" void kernel_launch(void* const* d_in, const int* in_sizes, int n_in,
                              void* d_out, int out_size)
{
    const float* x    = (const float*)d_in[0];
    const float* W    = (const float*)d_in[1];
    const float* bias = (const float*)d_in[2];
    float* out        = (float*)d_out;

    int T = in_sizes[0] / D_MODEL;  // 16384

    float* logits = nullptr;
    cudaGetSymbolAddress((void**)&logits, g_logits);

    // GEMM: one block per 64 tokens
    gemm_logits_kernel<<<T / BM, 256>>>(x, W, logits, T);

    // top-k: one warp per token, 8 warps/block
    int write_indices = (out_size >= 2 * T * TOP_K) ? 1 : 0;
    int nwarps = T;
    int blocks = (nwarps * 32 + 255) / 256;
    topk_softmax_kernel<<<blocks, 256>>>(logits, bias, out, T, write_indices);
}